// round 13
// baseline (speedup 1.0000x reference)
#include <cuda_runtime.h>
#include <cuda_fp16.h>
#include <cstdint>
#include <math.h>

#define DIM    1024
#define HEADS  16
#define DH     64
#define SEG    512
#define PMEM   16
#define BATCH  2
#define NSEQ   4096
#define WSEG   (NSEQ / SEG)       // 8
#define BW     (BATCH * WSEG)     // 16
#define ROWS   (BATCH * NSEQ)     // 8192
#define KV     (SEG + PMEM)       // 528
#define RMS_EPS 1.1920929e-07f
#define QSC (0.125f * 1.4426950408889634f)

// ---------------- scratch (no cudaMalloc allowed) ----------------
__device__ __half g_xnh[(size_t)ROWS * DIM];
__device__ __half g_whq[(size_t)3 * DIM * DIM];
__device__ __half g_who[(size_t)DIM * DIM];
__device__ __half g_q  [(size_t)BW * HEADS * SEG * DH];
__device__ __half g_k  [(size_t)BW * HEADS * KV  * DH];
__device__ __half g_v  [(size_t)BW * HEADS * KV  * DH];
__device__ __half g_aoh[(size_t)ROWS * DIM];

// ---------------- helpers ----------------
__device__ __forceinline__ float exp2p(float y) {
    y = fmaxf(y, -126.0f);
    float z = y + 12582912.0f;
    int   n = __float_as_int(z) - 0x4B400000;
    float f = y - (z - 12582912.0f);
    float p = 1.33336e-3f;
    p = fmaf(p, f, 9.61813e-3f);
    p = fmaf(p, f, 5.55041e-2f);
    p = fmaf(p, f, 2.40226502e-1f);
    p = fmaf(p, f, 6.93147182e-1f);
    p = fmaf(p, f, 1.0f);
    return p * __int_as_float((n + 127) << 23);
}

__device__ __forceinline__ void mma_f16(float c[4], unsigned a0, unsigned a1, unsigned a2,
                                        unsigned a3, unsigned b0, unsigned b1) {
    asm volatile(
        "mma.sync.aligned.m16n8k16.row.col.f32.f16.f16.f32 "
        "{%0,%1,%2,%3}, {%4,%5,%6,%7}, {%8,%9}, {%0,%1,%2,%3};"
        : "+f"(c[0]), "+f"(c[1]), "+f"(c[2]), "+f"(c[3])
        : "r"(a0), "r"(a1), "r"(a2), "r"(a3), "r"(b0), "r"(b1));
}

__device__ __forceinline__ void ldsm4(unsigned r[4], unsigned addr) {
    asm volatile("ldmatrix.sync.aligned.m8n8.x4.shared.b16 {%0,%1,%2,%3}, [%4];"
                 : "=r"(r[0]), "=r"(r[1]), "=r"(r[2]), "=r"(r[3]) : "r"(addr));
}

__device__ __forceinline__ void ldsm4t(unsigned r[4], unsigned addr) {
    asm volatile("ldmatrix.sync.aligned.m8n8.x4.trans.shared.b16 {%0,%1,%2,%3}, [%4];"
                 : "=r"(r[0]), "=r"(r[1]), "=r"(r[2]), "=r"(r[3]) : "r"(addr));
}

__device__ __forceinline__ unsigned packh2(float lo, float hi) {
    __half2 h = __floats2half2_rn(lo, hi);
    return *(unsigned*)&h;
}

__device__ __forceinline__ void cpasync16(unsigned dst, const void* src) {
    asm volatile("cp.async.ca.shared.global [%0], [%1], 16;" :: "r"(dst), "l"(src));
}
__device__ __forceinline__ void cpasync16z(unsigned dst, const void* src, bool valid) {
    unsigned v = valid ? 16u : 0u;
    asm volatile("cp.async.ca.shared.global [%0], [%1], 16, %2;"
                 :: "r"(dst), "l"(src), "r"(v));
}
__device__ __forceinline__ void cpcommit() {
    asm volatile("cp.async.commit_group;");
}
template <int N>
__device__ __forceinline__ void cpwait() {
    asm volatile("cp.async.wait_group %0;" :: "n"(N));
}

// ---------------- weight fp32 -> fp16 ----------------
__global__ __launch_bounds__(256) void f2h_kernel(const float* __restrict__ s,
                                                  __half* __restrict__ d, int n4) {
    int i = blockIdx.x * 256 + threadIdx.x;
    if (i < n4) {
        float4 v = ((const float4*)s)[i];
        __half2 h0 = __floats2half2_rn(v.x, v.y);
        __half2 h1 = __floats2half2_rn(v.z, v.w);
        ((uint2*)d)[i] = make_uint2(*(unsigned*)&h0, *(unsigned*)&h1);
    }
}

// ---------------- RMSNorm (fp16 out) ----------------
__global__ __launch_bounds__(256) void rmsnorm_kernel(const float* __restrict__ seq,
                                                      const float* __restrict__ g,
                                                      __half* __restrict__ xnh) {
    int row = blockIdx.x;
    int tid = threadIdx.x;
    const float4* in = (const float4*)(seq + (size_t)row * DIM);
    float4 v = in[tid];
    float ss = v.x * v.x + v.y * v.y + v.z * v.z + v.w * v.w;
    #pragma unroll
    for (int o = 16; o; o >>= 1) ss += __shfl_xor_sync(0xFFFFFFFFu, ss, o);
    __shared__ float wsum[8];
    __shared__ float srms;
    if ((tid & 31) == 0) wsum[tid >> 5] = ss;
    __syncthreads();
    if (tid == 0) {
        float t = 0.f;
        #pragma unroll
        for (int i = 0; i < 8; i++) t += wsum[i];
        srms = rsqrtf(t * (1.0f / DIM) + RMS_EPS);
    }
    __syncthreads();
    float r = srms;
    float4 gv = ((const float4*)g)[tid];
    __half2 h0 = __floats2half2_rn(v.x * r * gv.x, v.y * r * gv.y);
    __half2 h1 = __floats2half2_rn(v.z * r * gv.z, v.w * r * gv.w);
    ((uint2*)(xnh + (size_t)row * DIM))[tid] = make_uint2(*(unsigned*)&h0, *(unsigned*)&h1);
}

// ---------------- FP16 GEMM: C = A * B^T, 128x256 CTA, warp 64x64 ------------------
// QKV=true: fused RoPE + segment scatter epilogue into q/k/v (half).
#define BM 128
#define BN 256
#define KC 64
#define HS 72
#define A_BYTES (BM * HS * 2)                  // 18432
#define B_BYTES (BN * HS * 2)                  // 36864
#define STAGE_BYTES (A_BYTES + B_BYTES)        // 55296
#define GEMM_SMEM (2 * STAGE_BYTES)            // 110592

template <bool QKV>
__global__ __launch_bounds__(256, 1) void hgemm(const __half* __restrict__ A,
                                                const __half* __restrict__ Bm,
                                                float* __restrict__ C,
                                                __half* __restrict__ qo,
                                                __half* __restrict__ ko,
                                                __half* __restrict__ vo,
                                                int Nn, int K) {
    extern __shared__ __half sh[];
    unsigned smem_base = (unsigned)__cvta_generic_to_shared(sh);

    int tid = threadIdx.x;
    int bm = blockIdx.y * BM;
    int bn = blockIdx.x * BN;

    int wid  = tid >> 5;
    int lane = tid & 31;
    int warp_m = (wid & 1) * 64;
    int warp_n = (wid >> 1) * 64;
    int grp = lane >> 2;
    int qid = lane & 3;

    float c[4][8][4];
    #pragma unroll
    for (int i = 0; i < 4; i++)
        #pragma unroll
        for (int j = 0; j < 8; j++)
            #pragma unroll
            for (int u = 0; u < 4; u++) c[i][j][u] = 0.f;

    const int NT = K / KC;

    auto issue = [&](int kt, int s) {
        unsigned sb = smem_base + (unsigned)(s * STAGE_BYTES);
        int k0 = kt * KC;
        #pragma unroll
        for (int i = 0; i < 4; i++) {        // A: 1024 chunks
            int chunk = tid + 256 * i;
            int row = chunk >> 3;            // 0..127
            int c8 = (chunk & 7) * 8;
            cpasync16(sb + (unsigned)(row * HS + c8) * 2,
                      A + (size_t)(bm + row) * K + k0 + c8);
        }
        #pragma unroll
        for (int i = 0; i < 8; i++) {        // B: 2048 chunks
            int chunk = tid + 256 * i;
            int row = chunk >> 3;            // 0..255
            int c8 = (chunk & 7) * 8;
            cpasync16(sb + (unsigned)A_BYTES + (unsigned)(row * HS + c8) * 2,
                      Bm + (size_t)(bn + row) * K + k0 + c8);
        }
        cpcommit();
    };

    int aRow = warp_m + (lane & 15);
    int aCol = (lane & 16) >> 1;
    int nOff = (lane & 7) | ((lane & 16) >> 1);
    int kOff = lane & 8;

    issue(0, 0);

    for (int kt = 0; kt < NT; kt++) {
        cpwait<0>();
        __syncthreads();
        if (kt + 1 < NT) issue(kt + 1, (kt + 1) & 1);

        unsigned sb = smem_base + (unsigned)((kt & 1) * STAGE_BYTES);
        unsigned aAddr = sb + (unsigned)(aRow * HS + aCol) * 2;
        unsigned bAddr = sb + (unsigned)A_BYTES + (unsigned)((warp_n + nOff) * HS + kOff) * 2;

        #pragma unroll
        for (int ks = 0; ks < 4; ks++) {
            unsigned a[4][4];
            #pragma unroll
            for (int mf = 0; mf < 4; mf++)
                ldsm4(a[mf], aAddr + (unsigned)(mf * 16 * HS * 2) + ks * 32);
            #pragma unroll
            for (int nt = 0; nt < 4; nt++) {
                unsigned b[4];
                ldsm4(b, bAddr + (unsigned)(nt * 16 * HS * 2) + ks * 32);
                #pragma unroll
                for (int mf = 0; mf < 4; mf++) {
                    mma_f16(c[mf][2 * nt    ], a[mf][0], a[mf][1], a[mf][2], a[mf][3], b[0], b[1]);
                    mma_f16(c[mf][2 * nt + 1], a[mf][0], a[mf][1], a[mf][2], a[mf][3], b[2], b[3]);
                }
            }
        }
    }

    if (!QKV) {
        #pragma unroll
        for (int mf = 0; mf < 4; mf++) {
            int row0 = bm + warp_m + mf * 16 + grp;
            #pragma unroll
            for (int nf = 0; nf < 8; nf++) {
                int col = bn + warp_n + nf * 8 + qid * 2;
                *(float2*)(C + (size_t)row0 * Nn + col)       = make_float2(c[mf][nf][0], c[mf][nf][1]);
                *(float2*)(C + (size_t)(row0 + 8) * Nn + col) = make_float2(c[mf][nf][2], c[mf][nf][3]);
            }
        }
    } else {
        int which = (bn + warp_n) >> 10;     // uniform per warp (warp_n 64-aligned)
        float invf[8];
        if (which != 2) {
            #pragma unroll
            for (int nf = 0; nf < 8; nf++) {
                int d = (bn + warp_n + nf * 8 + qid * 2) & 63;
                invf[nf] = 1.0f / powf(10000.0f, (float)d * (1.0f / 64.0f));
            }
        }
        #pragma unroll
        for (int mf = 0; mf < 4; mf++) {
            #pragma unroll
            for (int sub = 0; sub < 2; sub++) {
                int m = bm + warp_m + mf * 16 + grp + sub * 8;
                int b = m >> 12;
                int npos = m & 4095;
                int w = npos >> 9;
                int sidx = npos & 511;
                int bwx = (b * WSEG + w) * HEADS;
                #pragma unroll
                for (int nf = 0; nf < 8; nf++) {
                    int col = bn + warp_n + nf * 8 + qid * 2;
                    int h = (col >> 6) & 15;
                    int d = col & 63;
                    float x = c[mf][nf][2 * sub], y = c[mf][nf][2 * sub + 1];
                    int bwh = bwx + h;
                    if (which == 2) {
                        *(unsigned*)(vo + ((size_t)bwh * KV + PMEM + sidx) * DH + d) = packh2(x, y);
                    } else {
                        float ang = (float)npos * invf[nf];
                        float sn, cs;
                        sincosf(ang, &sn, &cs);
                        float rx = x * cs - y * sn;
                        float ry = y * cs + x * sn;
                        if (which == 0)
                            *(unsigned*)(qo + ((size_t)bwh * SEG + sidx) * DH + d) = packh2(rx * QSC, ry * QSC);
                        else
                            *(unsigned*)(ko + ((size_t)bwh * KV + PMEM + sidx) * DH + d) = packh2(rx, ry);
                    }
                }
            }
        }
    }
}

// ---------------- persistent-memory prepend (half) ----------------
__global__ __launch_bounds__(1024) void pm_fill(const float* __restrict__ pm,
                                                __half* __restrict__ k,
                                                __half* __restrict__ v) {
    int bwh = blockIdx.x;
    int h = bwh & 15;
    int t = threadIdx.x;
    int p = t >> 6;
    int d = t & 63;
    float kv_ = pm[((size_t)h * PMEM + p) * DH + d];
    float vv_ = pm[(size_t)HEADS * PMEM * DH + ((size_t)h * PMEM + p) * DH + d];
    k[((size_t)bwh * KV + p) * DH + d] = __float2half(kv_);
    v[((size_t)bwh * KV + p) * DH + d] = __float2half(vv_);
}

// ---------------- fp16 flash attention, single-sync 2-stage cp.async --------------
#define SH2 72
#define QBYTES (128 * SH2 * 2)
#define KVBYTES (64 * SH2 * 2)
#define ATT_SMEM (QBYTES + 4 * KVBYTES)

__global__ __launch_bounds__(256) void attn_tc(const __half* __restrict__ Q,
                                               const __half* __restrict__ K,
                                               const __half* __restrict__ V,
                                               __half* __restrict__ AO) {
    extern __shared__ __half ash[];
    unsigned sbase = (unsigned)__cvta_generic_to_shared(ash);

    const int tid  = threadIdx.x;
    const int wid  = tid >> 5;
    const int lane = tid & 31;
    const int grp  = lane >> 2;
    const int qid  = lane & 3;
    const int bwh  = blockIdx.y;
    const int q0   = blockIdx.x * 128;
    const int wq0  = q0 + wid * 16;

    const __half* Qb = Q + (size_t)bwh * SEG * DH;
    const __half* Kb = K + (size_t)bwh * KV * DH;
    const __half* Vb = V + (size_t)bwh * KV * DH;

    const int r  = tid >> 2;
    const int c4 = tid & 3;

    int jmax = q0 + 128 + PMEM;
    if (jmax > KV) jmax = KV;
    int ntiles = (jmax + 63) >> 6;

    auto issueKV = [&](int t, int s) {
        unsigned kb = sbase + (unsigned)(QBYTES + s * 2 * KVBYTES);
        unsigned vb = kb + KVBYTES;
        int jj = t * 64 + r;
        bool valid = jj < KV;
        int jjc = valid ? jj : (KV - 1);
        const __half* kg = Kb + (size_t)jjc * DH + c4 * 16;
        const __half* vg = Vb + (size_t)jjc * DH + c4 * 16;
        unsigned off = (unsigned)(r * SH2 + c4 * 16) * 2;
        cpasync16z(kb + off,      kg,     valid);
        cpasync16z(kb + off + 16, kg + 8, valid);
        cpasync16z(vb + off,      vg,     valid);
        cpasync16z(vb + off + 16, vg + 8, valid);
        cpcommit();
    };

    issueKV(0, 0);

    {
        __half* sQp = ash;
        #pragma unroll
        for (int i = 0; i < 4; i++) {
            int chunk = tid + 256 * i;
            int row = chunk >> 3;
            int off = (chunk & 7) * 8;
            *(uint4*)(sQp + row * SH2 + off) = *(const uint4*)(Qb + (size_t)(q0 + row) * DH + off);
        }
    }
    __syncthreads();

    unsigned aq[4][4];
    {
        int aRow = wid * 16 + (lane & 15);
        int aCol = (lane & 16) >> 1;
        #pragma unroll
        for (int kc = 0; kc < 4; kc++)
            ldsm4(aq[kc], sbase + (unsigned)(aRow * SH2 + kc * 16 + aCol) * 2);
    }

    float o[8][4];
    #pragma unroll
    for (int nf = 0; nf < 8; nf++)
        #pragma unroll
        for (int u = 0; u < 4; u++) o[nf][u] = 0.f;
    float m0 = -1e30f, m1 = -1e30f, l0 = 0.f, l1 = 0.f;

    const int fRow = lane & 15;
    const int fCol = (lane & 16) >> 1;
    const int nRow = (lane & 7) | ((lane & 16) >> 1);
    const int kOff = lane & 8;

    for (int t = 0; t < ntiles; t++) {
        int jj0 = t << 6;
        cpwait<0>();
        __syncthreads();
        if (t + 1 < ntiles) issueKV(t + 1, (t + 1) & 1);

        unsigned sKb = sbase + (unsigned)(QBYTES + (t & 1) * 2 * KVBYTES);
        unsigned sVb = sKb + KVBYTES;

        if (jj0 <= wq0 + 15 + PMEM) {
            float c[8][4];
            #pragma unroll
            for (int nf = 0; nf < 8; nf++)
                #pragma unroll
                for (int u = 0; u < 4; u++) c[nf][u] = 0.f;

            #pragma unroll
            for (int kc = 0; kc < 4; kc++) {
                #pragma unroll
                for (int ng = 0; ng < 4; ng++) {
                    unsigned b[4];
                    ldsm4(b, sKb + (unsigned)((ng * 16 + nRow) * SH2 + kc * 16 + kOff) * 2);
                    mma_f16(c[2 * ng    ], aq[kc][0], aq[kc][1], aq[kc][2], aq[kc][3], b[0], b[1]);
                    mma_f16(c[2 * ng + 1], aq[kc][0], aq[kc][1], aq[kc][2], aq[kc][3], b[2], b[3]);
                }
            }

            if (jj0 + 63 > wq0 + PMEM) {
                int r0 = wq0 + grp, r1 = r0 + 8;
                #pragma unroll
                for (int nf = 0; nf < 8; nf++) {
                    int j0 = jj0 + nf * 8 + 2 * qid;
                    if (j0     - PMEM > r0) c[nf][0] = -1e30f;
                    if (j0 + 1 - PMEM > r0) c[nf][1] = -1e30f;
                    if (j0     - PMEM > r1) c[nf][2] = -1e30f;
                    if (j0 + 1 - PMEM > r1) c[nf][3] = -1e30f;
                }
            }

            float mt0 = -1e30f, mt1 = -1e30f;
            #pragma unroll
            for (int nf = 0; nf < 8; nf++) {
                mt0 = fmaxf(mt0, fmaxf(c[nf][0], c[nf][1]));
                mt1 = fmaxf(mt1, fmaxf(c[nf][2], c[nf][3]));
            }
            mt0 = fmaxf(mt0, __shfl_xor_sync(0xFFFFFFFFu, mt0, 1));
            mt0 = fmaxf(mt0, __shfl_xor_sync(0xFFFFFFFFu, mt0, 2));
            mt1 = fmaxf(mt1, __shfl_xor_sync(0xFFFFFFFFu, mt1, 1));
            mt1 = fmaxf(mt1, __shfl_xor_sync(0xFFFFFFFFu, mt1, 2));

            float nm0 = fmaxf(m0, mt0), nm1 = fmaxf(m1, mt1);
            float f0 = exp2p(m0 - nm0), f1 = exp2p(m1 - nm1);
            m0 = nm0; m1 = nm1;
            l0 *= f0; l1 *= f1;
            #pragma unroll
            for (int nf = 0; nf < 8; nf++) {
                o[nf][0] *= f0; o[nf][1] *= f0;
                o[nf][2] *= f1; o[nf][3] *= f1;
            }

            float s0 = 0.f, s1 = 0.f;
            #pragma unroll
            for (int nf = 0; nf < 8; nf++) {
                float p00 = exp2p(c[nf][0] - m0);
                float p01 = exp2p(c[nf][1] - m0);
                float p10 = exp2p(c[nf][2] - m1);
                float p11 = exp2p(c[nf][3] - m1);
                c[nf][0] = p00; c[nf][1] = p01; c[nf][2] = p10; c[nf][3] = p11;
                s0 += p00 + p01; s1 += p10 + p11;
            }
            s0 += __shfl_xor_sync(0xFFFFFFFFu, s0, 1);
            s0 += __shfl_xor_sync(0xFFFFFFFFu, s0, 2);
            s1 += __shfl_xor_sync(0xFFFFFFFFu, s1, 1);
            s1 += __shfl_xor_sync(0xFFFFFFFFu, s1, 2);
            l0 += s0; l1 += s1;

            unsigned ph[4][4];
            #pragma unroll
            for (int kc = 0; kc < 4; kc++) {
                ph[kc][0] = packh2(c[2 * kc    ][0], c[2 * kc    ][1]);
                ph[kc][1] = packh2(c[2 * kc    ][2], c[2 * kc    ][3]);
                ph[kc][2] = packh2(c[2 * kc + 1][0], c[2 * kc + 1][1]);
                ph[kc][3] = packh2(c[2 * kc + 1][2], c[2 * kc + 1][3]);
            }

            #pragma unroll
            for (int kc = 0; kc < 4; kc++) {
                #pragma unroll
                for (int dg = 0; dg < 4; dg++) {
                    unsigned b[4];
                    ldsm4t(b, sVb + (unsigned)((kc * 16 + fRow) * SH2 + dg * 16 + fCol) * 2);
                    mma_f16(o[2 * dg    ], ph[kc][0], ph[kc][1], ph[kc][2], ph[kc][3], b[0], b[1]);
                    mma_f16(o[2 * dg + 1], ph[kc][0], ph[kc][1], ph[kc][2], ph[kc][3], b[2], b[3]);
                }
            }
        }
    }

    float inv0 = 1.0f / l0, inv1 = 1.0f / l1;
    int bw = bwh >> 4, h = bwh & 15;
    int r0 = wq0 + grp, r1 = r0 + 8;
    __half* out0 = AO + (size_t)(bw * SEG + r0) * DIM + h * DH;
    __half* out1 = AO + (size_t)(bw * SEG + r1) * DIM + h * DH;
    #pragma unroll
    for (int nf = 0; nf < 8; nf++) {
        int col = nf * 8 + 2 * qid;
        *(unsigned*)(out0 + col) = packh2(o[nf][0] * inv0, o[nf][1] * inv0);
        *(unsigned*)(out1 + col) = packh2(o[nf][2] * inv1, o[nf][3] * inv1);
    }
}

// ---------------- launch ----------------
extern "C" void kernel_launch(void* const* d_in, const int* in_sizes, int n_in,
                              void* d_out, int out_size) {
    const float* seq   = (const float*)d_in[0];
    const float* g     = (const float*)d_in[1];
    const float* w_qkv = (const float*)d_in[2];
    const float* w_out = (const float*)d_in[3];
    const float* pm    = (const float*)d_in[4];
    float* out = (float*)d_out;

    __half *xnh, *whq, *who, *aoh, *q, *k, *v;
    cudaGetSymbolAddress((void**)&xnh, g_xnh);
    cudaGetSymbolAddress((void**)&whq, g_whq);
    cudaGetSymbolAddress((void**)&who, g_who);
    cudaGetSymbolAddress((void**)&q,   g_q);
    cudaGetSymbolAddress((void**)&k,   g_k);
    cudaGetSymbolAddress((void**)&v,   g_v);
    cudaGetSymbolAddress((void**)&aoh, g_aoh);

    static int smem_set = 0;
    if (!smem_set) {
        cudaFuncSetAttribute(hgemm<true>,  cudaFuncAttributeMaxDynamicSharedMemorySize, GEMM_SMEM);
        cudaFuncSetAttribute(hgemm<false>, cudaFuncAttributeMaxDynamicSharedMemorySize, GEMM_SMEM);
        cudaFuncSetAttribute(attn_tc, cudaFuncAttributeMaxDynamicSharedMemorySize, ATT_SMEM);
        smem_set = 1;
    }

    f2h_kernel<<<(3 * DIM * DIM / 4 + 255) / 256, 256>>>(w_qkv, whq, 3 * DIM * DIM / 4);
    f2h_kernel<<<(DIM * DIM / 4 + 255) / 256, 256>>>(w_out, who, DIM * DIM / 4);
    rmsnorm_kernel<<<ROWS, 256>>>(seq, g, xnh);
    pm_fill<<<BW * HEADS, 1024>>>(pm, k, v);
    hgemm<true><<<dim3(3 * DIM / BN, ROWS / BM), 256, GEMM_SMEM>>>(xnh, whq, nullptr, q, k, v, 3 * DIM, DIM);
    attn_tc<<<dim3(4, BW * HEADS), 256, ATT_SMEM>>>(q, k, v, aoh);
    hgemm<false><<<dim3(DIM / BN, ROWS / BM), 256, GEMM_SMEM>>>(aoh, who, out, nullptr, nullptr, nullptr, DIM, DIM);
}

// round 14
// speedup vs baseline: 1.1213x; 1.1213x over previous
#include <cuda_runtime.h>
#include <cuda_fp16.h>
#include <cstdint>
#include <math.h>

#define DIM    1024
#define HEADS  16
#define DH     64
#define SEG    512
#define PMEM   16
#define BATCH  2
#define NSEQ   4096
#define WSEG   (NSEQ / SEG)       // 8
#define BW     (BATCH * WSEG)     // 16
#define ROWS   (BATCH * NSEQ)     // 8192
#define KV     (SEG + PMEM)       // 528
#define RMS_EPS 1.1920929e-07f
#define QSC (0.125f * 1.4426950408889634f)

// ---------------- scratch (no cudaMalloc allowed) ----------------
__device__ __half g_xnh[(size_t)ROWS * DIM];
__device__ __half g_whq[(size_t)3 * DIM * DIM];
__device__ __half g_who[(size_t)DIM * DIM];
__device__ __half g_q  [(size_t)BW * HEADS * SEG * DH];
__device__ __half g_k  [(size_t)BW * HEADS * KV  * DH];
__device__ __half g_v  [(size_t)BW * HEADS * KV  * DH];
__device__ __half g_aoh[(size_t)ROWS * DIM];

// ---------------- helpers ----------------
__device__ __forceinline__ float exp2p(float y) {
    y = fmaxf(y, -126.0f);
    float z = y + 12582912.0f;
    int   n = __float_as_int(z) - 0x4B400000;
    float f = y - (z - 12582912.0f);
    float p = 1.33336e-3f;
    p = fmaf(p, f, 9.61813e-3f);
    p = fmaf(p, f, 5.55041e-2f);
    p = fmaf(p, f, 2.40226502e-1f);
    p = fmaf(p, f, 6.93147182e-1f);
    p = fmaf(p, f, 1.0f);
    return p * __int_as_float((n + 127) << 23);
}

__device__ __forceinline__ void mma_f16(float c[4], unsigned a0, unsigned a1, unsigned a2,
                                        unsigned a3, unsigned b0, unsigned b1) {
    asm volatile(
        "mma.sync.aligned.m16n8k16.row.col.f32.f16.f16.f32 "
        "{%0,%1,%2,%3}, {%4,%5,%6,%7}, {%8,%9}, {%0,%1,%2,%3};"
        : "+f"(c[0]), "+f"(c[1]), "+f"(c[2]), "+f"(c[3])
        : "r"(a0), "r"(a1), "r"(a2), "r"(a3), "r"(b0), "r"(b1));
}

__device__ __forceinline__ void ldsm4(unsigned r[4], unsigned addr) {
    asm volatile("ldmatrix.sync.aligned.m8n8.x4.shared.b16 {%0,%1,%2,%3}, [%4];"
                 : "=r"(r[0]), "=r"(r[1]), "=r"(r[2]), "=r"(r[3]) : "r"(addr));
}

__device__ __forceinline__ void ldsm4t(unsigned r[4], unsigned addr) {
    asm volatile("ldmatrix.sync.aligned.m8n8.x4.trans.shared.b16 {%0,%1,%2,%3}, [%4];"
                 : "=r"(r[0]), "=r"(r[1]), "=r"(r[2]), "=r"(r[3]) : "r"(addr));
}

__device__ __forceinline__ unsigned packh2(float lo, float hi) {
    __half2 h = __floats2half2_rn(lo, hi);
    return *(unsigned*)&h;
}

__device__ __forceinline__ void cpasync16(unsigned dst, const void* src) {
    asm volatile("cp.async.ca.shared.global [%0], [%1], 16;" :: "r"(dst), "l"(src));
}
__device__ __forceinline__ void cpasync16z(unsigned dst, const void* src, bool valid) {
    unsigned v = valid ? 16u : 0u;
    asm volatile("cp.async.ca.shared.global [%0], [%1], 16, %2;"
                 :: "r"(dst), "l"(src), "r"(v));
}
__device__ __forceinline__ void cpcommit() {
    asm volatile("cp.async.commit_group;");
}
template <int N>
__device__ __forceinline__ void cpwait() {
    asm volatile("cp.async.wait_group %0;" :: "n"(N));
}

// ---------------- weight fp32 -> fp16 ----------------
__global__ __launch_bounds__(256) void f2h_kernel(const float* __restrict__ s,
                                                  __half* __restrict__ d, int n4) {
    int i = blockIdx.x * 256 + threadIdx.x;
    if (i < n4) {
        float4 v = ((const float4*)s)[i];
        __half2 h0 = __floats2half2_rn(v.x, v.y);
        __half2 h1 = __floats2half2_rn(v.z, v.w);
        ((uint2*)d)[i] = make_uint2(*(unsigned*)&h0, *(unsigned*)&h1);
    }
}

// ---------------- RMSNorm (fp16 out) ----------------
__global__ __launch_bounds__(256) void rmsnorm_kernel(const float* __restrict__ seq,
                                                      const float* __restrict__ g,
                                                      __half* __restrict__ xnh) {
    int row = blockIdx.x;
    int tid = threadIdx.x;
    const float4* in = (const float4*)(seq + (size_t)row * DIM);
    float4 v = in[tid];
    float ss = v.x * v.x + v.y * v.y + v.z * v.z + v.w * v.w;
    #pragma unroll
    for (int o = 16; o; o >>= 1) ss += __shfl_xor_sync(0xFFFFFFFFu, ss, o);
    __shared__ float wsum[8];
    __shared__ float srms;
    if ((tid & 31) == 0) wsum[tid >> 5] = ss;
    __syncthreads();
    if (tid == 0) {
        float t = 0.f;
        #pragma unroll
        for (int i = 0; i < 8; i++) t += wsum[i];
        srms = rsqrtf(t * (1.0f / DIM) + RMS_EPS);
    }
    __syncthreads();
    float r = srms;
    float4 gv = ((const float4*)g)[tid];
    __half2 h0 = __floats2half2_rn(v.x * r * gv.x, v.y * r * gv.y);
    __half2 h1 = __floats2half2_rn(v.z * r * gv.z, v.w * r * gv.w);
    ((uint2*)(xnh + (size_t)row * DIM))[tid] = make_uint2(*(unsigned*)&h0, *(unsigned*)&h1);
}

// ---------------- FP16 GEMM: C = A * B^T, 128x128 CTA, 3-stage cp.async ------------
// QKV=true: fused RoPE + segment scatter epilogue into q/k/v (half).
#define BM 128
#define BN 128
#define KC 64
#define HS 72
#define SSZ (BM * HS)
#define STAGE_BYTES (2 * SSZ * 2)          // A+B per stage: 36864
#define GEMM_SMEM (3 * STAGE_BYTES)        // 110592

template <bool QKV>
__global__ __launch_bounds__(256) void hgemm(const __half* __restrict__ A,
                                             const __half* __restrict__ Bm,
                                             float* __restrict__ C,
                                             __half* __restrict__ qo,
                                             __half* __restrict__ ko,
                                             __half* __restrict__ vo,
                                             int Nn, int K) {
    extern __shared__ __half sh[];
    unsigned smem_base = (unsigned)__cvta_generic_to_shared(sh);

    int tid = threadIdx.x;
    int bm = blockIdx.y * BM;
    int bn = blockIdx.x * BN;

    int wid  = tid >> 5;
    int lane = tid & 31;
    int warp_m = (wid & 3) * 32;
    int warp_n = (wid >> 2) * 64;
    int grp = lane >> 2;
    int qid = lane & 3;

    float c[2][8][4];
    #pragma unroll
    for (int i = 0; i < 2; i++)
        #pragma unroll
        for (int j = 0; j < 8; j++)
            #pragma unroll
            for (int u = 0; u < 4; u++) c[i][j][u] = 0.f;

    const int NT = K / KC;   // 16

    auto issue = [&](int kt) {
        int s = kt % 3;
        unsigned sb = smem_base + (unsigned)(s * STAGE_BYTES);
        int k0 = kt * KC;
        #pragma unroll
        for (int i = 0; i < 4; i++) {
            int chunk = tid + 256 * i;
            int row = chunk >> 3;
            int c8 = (chunk & 7) * 8;
            unsigned off = (unsigned)(row * HS + c8) * 2;
            cpasync16(sb + off, A + (size_t)(bm + row) * K + k0 + c8);
            cpasync16(sb + (unsigned)(SSZ * 2) + off, Bm + (size_t)(bn + row) * K + k0 + c8);
        }
        cpcommit();
    };

    int aRow = warp_m + (lane & 15);
    int aCol = (lane & 16) >> 1;
    int nOff = (lane & 7) | ((lane & 16) >> 1);
    int kOff = lane & 8;

    issue(0);
    issue(1);

    for (int kt = 0; kt < NT; kt++) {
        cpwait<1>();                 // stage kt resident (kt+1 may be in flight)
        __syncthreads();
        if (kt + 2 < NT) issue(kt + 2);

        unsigned sb = smem_base + (unsigned)((kt % 3) * STAGE_BYTES);
        unsigned aAddr = sb + (unsigned)(aRow * HS + aCol) * 2;
        unsigned bAddr = sb + (unsigned)(SSZ * 2) + (unsigned)((warp_n + nOff) * HS + kOff) * 2;

        #pragma unroll
        for (int ks = 0; ks < 4; ks++) {
            unsigned a0[4], a1[4];
            ldsm4(a0, aAddr + ks * 32);
            ldsm4(a1, aAddr + (unsigned)(16 * HS * 2) + ks * 32);
            unsigned bf[4][4];
            #pragma unroll
            for (int nt = 0; nt < 4; nt++)
                ldsm4(bf[nt], bAddr + (unsigned)(nt * 16 * HS * 2) + ks * 32);
            #pragma unroll
            for (int nt = 0; nt < 4; nt++) {
                mma_f16(c[0][2 * nt    ], a0[0], a0[1], a0[2], a0[3], bf[nt][0], bf[nt][1]);
                mma_f16(c[0][2 * nt + 1], a0[0], a0[1], a0[2], a0[3], bf[nt][2], bf[nt][3]);
                mma_f16(c[1][2 * nt    ], a1[0], a1[1], a1[2], a1[3], bf[nt][0], bf[nt][1]);
                mma_f16(c[1][2 * nt + 1], a1[0], a1[1], a1[2], a1[3], bf[nt][2], bf[nt][3]);
            }
        }
    }

    if (!QKV) {
        #pragma unroll
        for (int mf = 0; mf < 2; mf++) {
            int row0 = bm + warp_m + mf * 16 + grp;
            #pragma unroll
            for (int nf = 0; nf < 8; nf++) {
                int col = bn + warp_n + nf * 8 + qid * 2;
                *(float2*)(C + (size_t)row0 * Nn + col)       = make_float2(c[mf][nf][0], c[mf][nf][1]);
                *(float2*)(C + (size_t)(row0 + 8) * Nn + col) = make_float2(c[mf][nf][2], c[mf][nf][3]);
            }
        }
    } else {
        int which = (bn + warp_n) >> 10;
        float invf[8];
        if (which != 2) {
            #pragma unroll
            for (int nf = 0; nf < 8; nf++) {
                int d = (bn + warp_n + nf * 8 + qid * 2) & 63;
                invf[nf] = 1.0f / powf(10000.0f, (float)d * (1.0f / 64.0f));
            }
        }
        #pragma unroll
        for (int mf = 0; mf < 2; mf++) {
            #pragma unroll
            for (int sub = 0; sub < 2; sub++) {
                int m = bm + warp_m + mf * 16 + grp + sub * 8;
                int b = m >> 12;
                int npos = m & 4095;
                int w = npos >> 9;
                int sidx = npos & 511;
                int bwx = (b * WSEG + w) * HEADS;
                #pragma unroll
                for (int nf = 0; nf < 8; nf++) {
                    int col = bn + warp_n + nf * 8 + qid * 2;
                    int h = (col >> 6) & 15;
                    int d = col & 63;
                    float x = c[mf][nf][2 * sub], y = c[mf][nf][2 * sub + 1];
                    int bwh = bwx + h;
                    if (which == 2) {
                        *(unsigned*)(vo + ((size_t)bwh * KV + PMEM + sidx) * DH + d) = packh2(x, y);
                    } else {
                        float ang = (float)npos * invf[nf];
                        float sn, cs;
                        sincosf(ang, &sn, &cs);
                        float rx = x * cs - y * sn;
                        float ry = y * cs + x * sn;
                        if (which == 0)
                            *(unsigned*)(qo + ((size_t)bwh * SEG + sidx) * DH + d) = packh2(rx * QSC, ry * QSC);
                        else
                            *(unsigned*)(ko + ((size_t)bwh * KV + PMEM + sidx) * DH + d) = packh2(rx, ry);
                    }
                }
            }
        }
    }
}

// ---------------- persistent-memory prepend (half) ----------------
__global__ __launch_bounds__(1024) void pm_fill(const float* __restrict__ pm,
                                                __half* __restrict__ k,
                                                __half* __restrict__ v) {
    int bwh = blockIdx.x;
    int h = bwh & 15;
    int t = threadIdx.x;
    int p = t >> 6;
    int d = t & 63;
    float kv_ = pm[((size_t)h * PMEM + p) * DH + d];
    float vv_ = pm[(size_t)HEADS * PMEM * DH + ((size_t)h * PMEM + p) * DH + d];
    k[((size_t)bwh * KV + p) * DH + d] = __float2half(kv_);
    v[((size_t)bwh * KV + p) * DH + d] = __float2half(vv_);
}

// ---------------- fp16 flash attention, 3-stage cp.async --------------
#define SH2 72
#define QBYTES (128 * SH2 * 2)
#define KVBYTES (64 * SH2 * 2)
#define KVSTAGE (2 * KVBYTES)
#define ATT_SMEM (QBYTES + 3 * KVSTAGE)     // 73728

__global__ __launch_bounds__(256) void attn_tc(const __half* __restrict__ Q,
                                               const __half* __restrict__ K,
                                               const __half* __restrict__ V,
                                               __half* __restrict__ AO) {
    extern __shared__ __half ash[];
    unsigned sbase = (unsigned)__cvta_generic_to_shared(ash);

    const int tid  = threadIdx.x;
    const int wid  = tid >> 5;
    const int lane = tid & 31;
    const int grp  = lane >> 2;
    const int qid  = lane & 3;
    const int bwh  = blockIdx.y;
    const int q0   = blockIdx.x * 128;
    const int wq0  = q0 + wid * 16;

    const __half* Qb = Q + (size_t)bwh * SEG * DH;
    const __half* Kb = K + (size_t)bwh * KV * DH;
    const __half* Vb = V + (size_t)bwh * KV * DH;

    const int r  = tid >> 2;
    const int c4 = tid & 3;

    int jmax = q0 + 128 + PMEM;
    if (jmax > KV) jmax = KV;
    int ntiles = (jmax + 63) >> 6;

    auto issueKV = [&](int t) {
        int s = t % 3;
        unsigned kb = sbase + (unsigned)(QBYTES + s * KVSTAGE);
        unsigned vb = kb + KVBYTES;
        int jj = t * 64 + r;
        bool valid = jj < KV;
        int jjc = valid ? jj : (KV - 1);
        const __half* kg = Kb + (size_t)jjc * DH + c4 * 16;
        const __half* vg = Vb + (size_t)jjc * DH + c4 * 16;
        unsigned off = (unsigned)(r * SH2 + c4 * 16) * 2;
        cpasync16z(kb + off,      kg,     valid);
        cpasync16z(kb + off + 16, kg + 8, valid);
        cpasync16z(vb + off,      vg,     valid);
        cpasync16z(vb + off + 16, vg + 8, valid);
        cpcommit();
    };

    issueKV(0);
    if (ntiles > 1) issueKV(1);

    {
        __half* sQp = ash;
        #pragma unroll
        for (int i = 0; i < 4; i++) {
            int chunk = tid + 256 * i;
            int row = chunk >> 3;
            int off = (chunk & 7) * 8;
            *(uint4*)(sQp + row * SH2 + off) = *(const uint4*)(Qb + (size_t)(q0 + row) * DH + off);
        }
    }
    __syncthreads();

    unsigned aq[4][4];
    {
        int aRow = wid * 16 + (lane & 15);
        int aCol = (lane & 16) >> 1;
        #pragma unroll
        for (int kc = 0; kc < 4; kc++)
            ldsm4(aq[kc], sbase + (unsigned)(aRow * SH2 + kc * 16 + aCol) * 2);
    }

    float o[8][4];
    #pragma unroll
    for (int nf = 0; nf < 8; nf++)
        #pragma unroll
        for (int u = 0; u < 4; u++) o[nf][u] = 0.f;
    float m0 = -1e30f, m1 = -1e30f, l0 = 0.f, l1 = 0.f;

    const int fRow = lane & 15;
    const int fCol = (lane & 16) >> 1;
    const int nRow = (lane & 7) | ((lane & 16) >> 1);
    const int kOff = lane & 8;

    for (int t = 0; t < ntiles; t++) {
        int jj0 = t << 6;
        if (t + 1 < ntiles) { cpwait<1>(); } else { cpwait<0>(); }
        __syncthreads();
        if (t + 2 < ntiles) issueKV(t + 2);

        unsigned sKb = sbase + (unsigned)(QBYTES + (t % 3) * KVSTAGE);
        unsigned sVb = sKb + KVBYTES;

        if (jj0 <= wq0 + 15 + PMEM) {
            float c[8][4];
            #pragma unroll
            for (int nf = 0; nf < 8; nf++)
                #pragma unroll
                for (int u = 0; u < 4; u++) c[nf][u] = 0.f;

            #pragma unroll
            for (int kc = 0; kc < 4; kc++) {
                #pragma unroll
                for (int ng = 0; ng < 4; ng++) {
                    unsigned b[4];
                    ldsm4(b, sKb + (unsigned)((ng * 16 + nRow) * SH2 + kc * 16 + kOff) * 2);
                    mma_f16(c[2 * ng    ], aq[kc][0], aq[kc][1], aq[kc][2], aq[kc][3], b[0], b[1]);
                    mma_f16(c[2 * ng + 1], aq[kc][0], aq[kc][1], aq[kc][2], aq[kc][3], b[2], b[3]);
                }
            }

            if (jj0 + 63 > wq0 + PMEM) {
                int r0 = wq0 + grp, r1 = r0 + 8;
                #pragma unroll
                for (int nf = 0; nf < 8; nf++) {
                    int j0 = jj0 + nf * 8 + 2 * qid;
                    if (j0     - PMEM > r0) c[nf][0] = -1e30f;
                    if (j0 + 1 - PMEM > r0) c[nf][1] = -1e30f;
                    if (j0     - PMEM > r1) c[nf][2] = -1e30f;
                    if (j0 + 1 - PMEM > r1) c[nf][3] = -1e30f;
                }
            }

            float mt0 = -1e30f, mt1 = -1e30f;
            #pragma unroll
            for (int nf = 0; nf < 8; nf++) {
                mt0 = fmaxf(mt0, fmaxf(c[nf][0], c[nf][1]));
                mt1 = fmaxf(mt1, fmaxf(c[nf][2], c[nf][3]));
            }
            mt0 = fmaxf(mt0, __shfl_xor_sync(0xFFFFFFFFu, mt0, 1));
            mt0 = fmaxf(mt0, __shfl_xor_sync(0xFFFFFFFFu, mt0, 2));
            mt1 = fmaxf(mt1, __shfl_xor_sync(0xFFFFFFFFu, mt1, 1));
            mt1 = fmaxf(mt1, __shfl_xor_sync(0xFFFFFFFFu, mt1, 2));

            float nm0 = fmaxf(m0, mt0), nm1 = fmaxf(m1, mt1);
            float f0 = exp2p(m0 - nm0), f1 = exp2p(m1 - nm1);
            m0 = nm0; m1 = nm1;
            l0 *= f0; l1 *= f1;
            #pragma unroll
            for (int nf = 0; nf < 8; nf++) {
                o[nf][0] *= f0; o[nf][1] *= f0;
                o[nf][2] *= f1; o[nf][3] *= f1;
            }

            float s0 = 0.f, s1 = 0.f;
            #pragma unroll
            for (int nf = 0; nf < 8; nf++) {
                float p00 = exp2p(c[nf][0] - m0);
                float p01 = exp2p(c[nf][1] - m0);
                float p10 = exp2p(c[nf][2] - m1);
                float p11 = exp2p(c[nf][3] - m1);
                c[nf][0] = p00; c[nf][1] = p01; c[nf][2] = p10; c[nf][3] = p11;
                s0 += p00 + p01; s1 += p10 + p11;
            }
            s0 += __shfl_xor_sync(0xFFFFFFFFu, s0, 1);
            s0 += __shfl_xor_sync(0xFFFFFFFFu, s0, 2);
            s1 += __shfl_xor_sync(0xFFFFFFFFu, s1, 1);
            s1 += __shfl_xor_sync(0xFFFFFFFFu, s1, 2);
            l0 += s0; l1 += s1;

            unsigned ph[4][4];
            #pragma unroll
            for (int kc = 0; kc < 4; kc++) {
                ph[kc][0] = packh2(c[2 * kc    ][0], c[2 * kc    ][1]);
                ph[kc][1] = packh2(c[2 * kc    ][2], c[2 * kc    ][3]);
                ph[kc][2] = packh2(c[2 * kc + 1][0], c[2 * kc + 1][1]);
                ph[kc][3] = packh2(c[2 * kc + 1][2], c[2 * kc + 1][3]);
            }

            #pragma unroll
            for (int kc = 0; kc < 4; kc++) {
                #pragma unroll
                for (int dg = 0; dg < 4; dg++) {
                    unsigned b[4];
                    ldsm4t(b, sVb + (unsigned)((kc * 16 + fRow) * SH2 + dg * 16 + fCol) * 2);
                    mma_f16(o[2 * dg    ], ph[kc][0], ph[kc][1], ph[kc][2], ph[kc][3], b[0], b[1]);
                    mma_f16(o[2 * dg + 1], ph[kc][0], ph[kc][1], ph[kc][2], ph[kc][3], b[2], b[3]);
                }
            }
        }
    }

    float inv0 = 1.0f / l0, inv1 = 1.0f / l1;
    int bw = bwh >> 4, h = bwh & 15;
    int r0 = wq0 + grp, r1 = r0 + 8;
    __half* out0 = AO + (size_t)(bw * SEG + r0) * DIM + h * DH;
    __half* out1 = AO + (size_t)(bw * SEG + r1) * DIM + h * DH;
    #pragma unroll
    for (int nf = 0; nf < 8; nf++) {
        int col = nf * 8 + 2 * qid;
        *(unsigned*)(out0 + col) = packh2(o[nf][0] * inv0, o[nf][1] * inv0);
        *(unsigned*)(out1 + col) = packh2(o[nf][2] * inv1, o[nf][3] * inv1);
    }
}

// ---------------- launch ----------------
extern "C" void kernel_launch(void* const* d_in, const int* in_sizes, int n_in,
                              void* d_out, int out_size) {
    const float* seq   = (const float*)d_in[0];
    const float* g     = (const float*)d_in[1];
    const float* w_qkv = (const float*)d_in[2];
    const float* w_out = (const float*)d_in[3];
    const float* pm    = (const float*)d_in[4];
    float* out = (float*)d_out;

    __half *xnh, *whq, *who, *aoh, *q, *k, *v;
    cudaGetSymbolAddress((void**)&xnh, g_xnh);
    cudaGetSymbolAddress((void**)&whq, g_whq);
    cudaGetSymbolAddress((void**)&who, g_who);
    cudaGetSymbolAddress((void**)&q,   g_q);
    cudaGetSymbolAddress((void**)&k,   g_k);
    cudaGetSymbolAddress((void**)&v,   g_v);
    cudaGetSymbolAddress((void**)&aoh, g_aoh);

    static int smem_set = 0;
    if (!smem_set) {
        cudaFuncSetAttribute(hgemm<true>,  cudaFuncAttributeMaxDynamicSharedMemorySize, GEMM_SMEM);
        cudaFuncSetAttribute(hgemm<false>, cudaFuncAttributeMaxDynamicSharedMemorySize, GEMM_SMEM);
        cudaFuncSetAttribute(attn_tc, cudaFuncAttributeMaxDynamicSharedMemorySize, ATT_SMEM);
        smem_set = 1;
    }

    // hgemm<true> placed 4th — profiler captures the 4th launch
    f2h_kernel<<<(3 * DIM * DIM / 4 + 255) / 256, 256>>>(w_qkv, whq, 3 * DIM * DIM / 4);
    f2h_kernel<<<(DIM * DIM / 4 + 255) / 256, 256>>>(w_out, who, DIM * DIM / 4);
    rmsnorm_kernel<<<ROWS, 256>>>(seq, g, xnh);
    hgemm<true><<<dim3(3 * DIM / BN, ROWS / BM), 256, GEMM_SMEM>>>(xnh, whq, nullptr, q, k, v, 3 * DIM, DIM);
    pm_fill<<<BW * HEADS, 1024>>>(pm, k, v);
    attn_tc<<<dim3(4, BW * HEADS), 256, ATT_SMEM>>>(q, k, v, aoh);
    hgemm<false><<<dim3(DIM / BN, ROWS / BM), 256, GEMM_SMEM>>>(aoh, who, out, nullptr, nullptr, nullptr, DIM, DIM);
}

// round 16
// speedup vs baseline: 1.1374x; 1.0144x over previous
#include <cuda_runtime.h>
#include <cuda_fp16.h>
#include <cstdint>
#include <math.h>

#define DIM    1024
#define HEADS  16
#define DH     64
#define SEG    512
#define PMEM   16
#define BATCH  2
#define NSEQ   4096
#define WSEG   (NSEQ / SEG)       // 8
#define BW     (BATCH * WSEG)     // 16
#define ROWS   (BATCH * NSEQ)     // 8192
#define KV     (SEG + PMEM)       // 528
#define RMS_EPS 1.1920929e-07f
#define QSC (0.125f * 1.4426950408889634f)

// ---------------- scratch (no cudaMalloc allowed) ----------------
__device__ __half g_xnh[(size_t)ROWS * DIM];
__device__ __half g_whq[(size_t)3 * DIM * DIM];
__device__ __half g_who[(size_t)DIM * DIM];
__device__ __half g_q  [(size_t)BW * HEADS * SEG * DH];
__device__ __half g_k  [(size_t)BW * HEADS * KV  * DH];
__device__ __half g_v  [(size_t)BW * HEADS * KV  * DH];
__device__ __half g_aoh[(size_t)ROWS * DIM];
__device__ float2 g_rope[(size_t)NSEQ * 32];     // [npos][d/2] = (cos, sin)

// ---------------- helpers ----------------
__device__ __forceinline__ float exp2p(float y) {
    y = fmaxf(y, -126.0f);
    float z = y + 12582912.0f;
    int   n = __float_as_int(z) - 0x4B400000;
    float f = y - (z - 12582912.0f);
    float p = 1.33336e-3f;
    p = fmaf(p, f, 9.61813e-3f);
    p = fmaf(p, f, 5.55041e-2f);
    p = fmaf(p, f, 2.40226502e-1f);
    p = fmaf(p, f, 6.93147182e-1f);
    p = fmaf(p, f, 1.0f);
    return p * __int_as_float((n + 127) << 23);
}

__device__ __forceinline__ void mma_f16(float c[4], unsigned a0, unsigned a1, unsigned a2,
                                        unsigned a3, unsigned b0, unsigned b1) {
    asm volatile(
        "mma.sync.aligned.m16n8k16.row.col.f32.f16.f16.f32 "
        "{%0,%1,%2,%3}, {%4,%5,%6,%7}, {%8,%9}, {%0,%1,%2,%3};"
        : "+f"(c[0]), "+f"(c[1]), "+f"(c[2]), "+f"(c[3])
        : "r"(a0), "r"(a1), "r"(a2), "r"(a3), "r"(b0), "r"(b1));
}

__device__ __forceinline__ void ldsm4(unsigned r[4], unsigned addr) {
    asm volatile("ldmatrix.sync.aligned.m8n8.x4.shared.b16 {%0,%1,%2,%3}, [%4];"
                 : "=r"(r[0]), "=r"(r[1]), "=r"(r[2]), "=r"(r[3]) : "r"(addr));
}

__device__ __forceinline__ void ldsm4t(unsigned r[4], unsigned addr) {
    asm volatile("ldmatrix.sync.aligned.m8n8.x4.trans.shared.b16 {%0,%1,%2,%3}, [%4];"
                 : "=r"(r[0]), "=r"(r[1]), "=r"(r[2]), "=r"(r[3]) : "r"(addr));
}

__device__ __forceinline__ unsigned packh2(float lo, float hi) {
    __half2 h = __floats2half2_rn(lo, hi);
    return *(unsigned*)&h;
}

__device__ __forceinline__ void cpasync16(unsigned dst, const void* src) {
    asm volatile("cp.async.ca.shared.global [%0], [%1], 16;" :: "r"(dst), "l"(src));
}
__device__ __forceinline__ void cpasync16z(unsigned dst, const void* src, bool valid) {
    unsigned v = valid ? 16u : 0u;
    asm volatile("cp.async.ca.shared.global [%0], [%1], 16, %2;"
                 :: "r"(dst), "l"(src), "r"(v));
}
__device__ __forceinline__ void cpcommit() {
    asm volatile("cp.async.commit_group;");
}
template <int N>
__device__ __forceinline__ void cpwait() {
    asm volatile("cp.async.wait_group %0;" :: "n"(N));
}

// ---------------- RoPE table init ----------------
__global__ __launch_bounds__(256) void rope_init(float2* __restrict__ tab) {
    int i = blockIdx.x * 256 + threadIdx.x;     // 0..131071
    if (i < NSEQ * 32) {
        int npos = i >> 5;
        int f = i & 31;
        float inv = 1.0f / powf(10000.0f, (float)(2 * f) * (1.0f / 64.0f));
        float sn, cs;
        sincosf((float)npos * inv, &sn, &cs);
        tab[i] = make_float2(cs, sn);
    }
}

// ---------------- weight fp32 -> fp16 ----------------
__global__ __launch_bounds__(256) void f2h_kernel(const float* __restrict__ s,
                                                  __half* __restrict__ d, int n4) {
    int i = blockIdx.x * 256 + threadIdx.x;
    if (i < n4) {
        float4 v = ((const float4*)s)[i];
        __half2 h0 = __floats2half2_rn(v.x, v.y);
        __half2 h1 = __floats2half2_rn(v.z, v.w);
        ((uint2*)d)[i] = make_uint2(*(unsigned*)&h0, *(unsigned*)&h1);
    }
}

// ---------------- RMSNorm (fp16 out) ----------------
__global__ __launch_bounds__(256) void rmsnorm_kernel(const float* __restrict__ seq,
                                                      const float* __restrict__ g,
                                                      __half* __restrict__ xnh) {
    int row = blockIdx.x;
    int tid = threadIdx.x;
    const float4* in = (const float4*)(seq + (size_t)row * DIM);
    float4 v = in[tid];
    float ss = v.x * v.x + v.y * v.y + v.z * v.z + v.w * v.w;
    #pragma unroll
    for (int o = 16; o; o >>= 1) ss += __shfl_xor_sync(0xFFFFFFFFu, ss, o);
    __shared__ float wsum[8];
    __shared__ float srms;
    if ((tid & 31) == 0) wsum[tid >> 5] = ss;
    __syncthreads();
    if (tid == 0) {
        float t = 0.f;
        #pragma unroll
        for (int i = 0; i < 8; i++) t += wsum[i];
        srms = rsqrtf(t * (1.0f / DIM) + RMS_EPS);
    }
    __syncthreads();
    float r = srms;
    float4 gv = ((const float4*)g)[tid];
    __half2 h0 = __floats2half2_rn(v.x * r * gv.x, v.y * r * gv.y);
    __half2 h1 = __floats2half2_rn(v.z * r * gv.z, v.w * r * gv.w);
    ((uint2*)(xnh + (size_t)row * DIM))[tid] = make_uint2(*(unsigned*)&h0, *(unsigned*)&h1);
}

// ---------------- FP16 GEMM: C = A * B^T, 128x128 CTA, 2-stage single-sync --------
// QKV=true: fused RoPE (table) + segment scatter epilogue into q/k/v (half).
#define BM 128
#define BN 128
#define KC 64
#define HS 72
#define SSZ (BM * HS)
#define GEMM_SMEM (2 * 2 * SSZ * 2)     // 73728

template <bool QKV>
__global__ __launch_bounds__(256) void hgemm(const __half* __restrict__ A,
                                             const __half* __restrict__ Bm,
                                             float* __restrict__ C,
                                             __half* __restrict__ qo,
                                             __half* __restrict__ ko,
                                             __half* __restrict__ vo,
                                             const float2* __restrict__ rope,
                                             int Nn, int K) {
    extern __shared__ __half sh[];
    unsigned smem_base = (unsigned)__cvta_generic_to_shared(sh);

    int tid = threadIdx.x;
    int bm = blockIdx.y * BM;
    int bn = blockIdx.x * BN;

    int wid  = tid >> 5;
    int lane = tid & 31;
    int warp_m = (wid & 3) * 32;
    int warp_n = (wid >> 2) * 64;
    int grp = lane >> 2;
    int qid = lane & 3;

    float c[2][8][4];
    #pragma unroll
    for (int i = 0; i < 2; i++)
        #pragma unroll
        for (int j = 0; j < 8; j++)
            #pragma unroll
            for (int u = 0; u < 4; u++) c[i][j][u] = 0.f;

    const int NT = K / KC;

    auto issue = [&](int kt, int s) {
        unsigned sb = smem_base + (unsigned)(s * 2 * SSZ * 2);
        int k0 = kt * KC;
        #pragma unroll
        for (int i = 0; i < 4; i++) {
            int chunk = tid + 256 * i;
            int row = chunk >> 3;
            int c8 = (chunk & 7) * 8;
            unsigned off = (unsigned)(row * HS + c8) * 2;
            cpasync16(sb + off, A + (size_t)(bm + row) * K + k0 + c8);
            cpasync16(sb + (unsigned)(SSZ * 2) + off, Bm + (size_t)(bn + row) * K + k0 + c8);
        }
        cpcommit();
    };

    int aRow = warp_m + (lane & 15);
    int aCol = (lane & 16) >> 1;
    int nOff = (lane & 7) | ((lane & 16) >> 1);
    int kOff = lane & 8;

    issue(0, 0);

    for (int kt = 0; kt < NT; kt++) {
        cpwait<0>();
        __syncthreads();
        if (kt + 1 < NT) issue(kt + 1, (kt + 1) & 1);

        unsigned sb = smem_base + (unsigned)((kt & 1) * 2 * SSZ * 2);
        unsigned aAddr = sb + (unsigned)(aRow * HS + aCol) * 2;
        unsigned bAddr = sb + (unsigned)(SSZ * 2) + (unsigned)((warp_n + nOff) * HS + kOff) * 2;

        #pragma unroll
        for (int ks = 0; ks < 4; ks++) {
            unsigned a0[4], a1[4];
            ldsm4(a0, aAddr + ks * 32);
            ldsm4(a1, aAddr + (unsigned)(16 * HS * 2) + ks * 32);
            unsigned bf[4][4];
            #pragma unroll
            for (int nt = 0; nt < 4; nt++)
                ldsm4(bf[nt], bAddr + (unsigned)(nt * 16 * HS * 2) + ks * 32);
            #pragma unroll
            for (int nt = 0; nt < 4; nt++) {
                mma_f16(c[0][2 * nt    ], a0[0], a0[1], a0[2], a0[3], bf[nt][0], bf[nt][1]);
                mma_f16(c[0][2 * nt + 1], a0[0], a0[1], a0[2], a0[3], bf[nt][2], bf[nt][3]);
                mma_f16(c[1][2 * nt    ], a1[0], a1[1], a1[2], a1[3], bf[nt][0], bf[nt][1]);
                mma_f16(c[1][2 * nt + 1], a1[0], a1[1], a1[2], a1[3], bf[nt][2], bf[nt][3]);
            }
        }
    }

    if (!QKV) {
        #pragma unroll
        for (int mf = 0; mf < 2; mf++) {
            int row0 = bm + warp_m + mf * 16 + grp;
            #pragma unroll
            for (int nf = 0; nf < 8; nf++) {
                int col = bn + warp_n + nf * 8 + qid * 2;
                *(float2*)(C + (size_t)row0 * Nn + col)       = make_float2(c[mf][nf][0], c[mf][nf][1]);
                *(float2*)(C + (size_t)(row0 + 8) * Nn + col) = make_float2(c[mf][nf][2], c[mf][nf][3]);
            }
        }
    } else {
        int which = (bn + warp_n) >> 10;     // uniform per warp
        #pragma unroll
        for (int mf = 0; mf < 2; mf++) {
            #pragma unroll
            for (int sub = 0; sub < 2; sub++) {
                int m = bm + warp_m + mf * 16 + grp + sub * 8;
                int b = m >> 12;
                int npos = m & 4095;
                int w = npos >> 9;
                int sidx = npos & 511;
                int bwx = (b * WSEG + w) * HEADS;
                const float2* rrow = rope + (size_t)npos * 32;
                #pragma unroll
                for (int nf = 0; nf < 8; nf++) {
                    int col = bn + warp_n + nf * 8 + qid * 2;
                    int h = (col >> 6) & 15;
                    int d = col & 63;
                    float x = c[mf][nf][2 * sub], y = c[mf][nf][2 * sub + 1];
                    int bwh = bwx + h;
                    if (which == 2) {
                        *(unsigned*)(vo + ((size_t)bwh * KV + PMEM + sidx) * DH + d) = packh2(x, y);
                    } else {
                        float2 rt = __ldg(rrow + (d >> 1));
                        float rx = x * rt.x - y * rt.y;
                        float ry = y * rt.x + x * rt.y;
                        if (which == 0)
                            *(unsigned*)(qo + ((size_t)bwh * SEG + sidx) * DH + d) = packh2(rx * QSC, ry * QSC);
                        else
                            *(unsigned*)(ko + ((size_t)bwh * KV + PMEM + sidx) * DH + d) = packh2(rx, ry);
                    }
                }
            }
        }
    }
}

// ---------------- persistent-memory prepend (half) ----------------
__global__ __launch_bounds__(1024) void pm_fill(const float* __restrict__ pm,
                                                __half* __restrict__ k,
                                                __half* __restrict__ v) {
    int bwh = blockIdx.x;
    int h = bwh & 15;
    int t = threadIdx.x;
    int p = t >> 6;
    int d = t & 63;
    float kv_ = pm[((size_t)h * PMEM + p) * DH + d];
    float vv_ = pm[(size_t)HEADS * PMEM * DH + ((size_t)h * PMEM + p) * DH + d];
    k[((size_t)bwh * KV + p) * DH + d] = __float2half(kv_);
    v[((size_t)bwh * KV + p) * DH + d] = __float2half(vv_);
}

// ---------------- fp16 flash attention, 2-stage single-sync cp.async --------------
#define SH2 72
#define QBYTES (128 * SH2 * 2)
#define KVBYTES (64 * SH2 * 2)
#define ATT_SMEM (QBYTES + 4 * KVBYTES)

__global__ __launch_bounds__(256) void attn_tc(const __half* __restrict__ Q,
                                               const __half* __restrict__ K,
                                               const __half* __restrict__ V,
                                               __half* __restrict__ AO) {
    extern __shared__ __half ash[];
    unsigned sbase = (unsigned)__cvta_generic_to_shared(ash);

    const int tid  = threadIdx.x;
    const int wid  = tid >> 5;
    const int lane = tid & 31;
    const int grp  = lane >> 2;
    const int qid  = lane & 3;
    const int bwh  = blockIdx.y;
    const int q0   = blockIdx.x * 128;
    const int wq0  = q0 + wid * 16;

    const __half* Qb = Q + (size_t)bwh * SEG * DH;
    const __half* Kb = K + (size_t)bwh * KV * DH;
    const __half* Vb = V + (size_t)bwh * KV * DH;

    const int r  = tid >> 2;
    const int c4 = tid & 3;

    int jmax = q0 + 128 + PMEM;
    if (jmax > KV) jmax = KV;
    int ntiles = (jmax + 63) >> 6;

    auto issueKV = [&](int t, int s) {
        unsigned kb = sbase + (unsigned)(QBYTES + s * 2 * KVBYTES);
        unsigned vb = kb + KVBYTES;
        int jj = t * 64 + r;
        bool valid = jj < KV;
        int jjc = valid ? jj : (KV - 1);
        const __half* kg = Kb + (size_t)jjc * DH + c4 * 16;
        const __half* vg = Vb + (size_t)jjc * DH + c4 * 16;
        unsigned off = (unsigned)(r * SH2 + c4 * 16) * 2;
        cpasync16z(kb + off,      kg,     valid);
        cpasync16z(kb + off + 16, kg + 8, valid);
        cpasync16z(vb + off,      vg,     valid);
        cpasync16z(vb + off + 16, vg + 8, valid);
        cpcommit();
    };

    issueKV(0, 0);

    {
        __half* sQp = ash;
        #pragma unroll
        for (int i = 0; i < 4; i++) {
            int chunk = tid + 256 * i;
            int row = chunk >> 3;
            int off = (chunk & 7) * 8;
            *(uint4*)(sQp + row * SH2 + off) = *(const uint4*)(Qb + (size_t)(q0 + row) * DH + off);
        }
    }
    __syncthreads();

    unsigned aq[4][4];
    {
        int aRow = wid * 16 + (lane & 15);
        int aCol = (lane & 16) >> 1;
        #pragma unroll
        for (int kc = 0; kc < 4; kc++)
            ldsm4(aq[kc], sbase + (unsigned)(aRow * SH2 + kc * 16 + aCol) * 2);
    }

    float o[8][4];
    #pragma unroll
    for (int nf = 0; nf < 8; nf++)
        #pragma unroll
        for (int u = 0; u < 4; u++) o[nf][u] = 0.f;
    float m0 = -1e30f, m1 = -1e30f, l0 = 0.f, l1 = 0.f;

    const int fRow = lane & 15;
    const int fCol = (lane & 16) >> 1;
    const int nRow = (lane & 7) | ((lane & 16) >> 1);
    const int kOff = lane & 8;

    for (int t = 0; t < ntiles; t++) {
        int jj0 = t << 6;
        cpwait<0>();
        __syncthreads();
        if (t + 1 < ntiles) issueKV(t + 1, (t + 1) & 1);

        unsigned sKb = sbase + (unsigned)(QBYTES + (t & 1) * 2 * KVBYTES);
        unsigned sVb = sKb + KVBYTES;

        if (jj0 <= wq0 + 15 + PMEM) {
            float c[8][4];
            #pragma unroll
            for (int nf = 0; nf < 8; nf++)
                #pragma unroll
                for (int u = 0; u < 4; u++) c[nf][u] = 0.f;

            #pragma unroll
            for (int kc = 0; kc < 4; kc++) {
                #pragma unroll
                for (int ng = 0; ng < 4; ng++) {
                    unsigned b[4];
                    ldsm4(b, sKb + (unsigned)((ng * 16 + nRow) * SH2 + kc * 16 + kOff) * 2);
                    mma_f16(c[2 * ng    ], aq[kc][0], aq[kc][1], aq[kc][2], aq[kc][3], b[0], b[1]);
                    mma_f16(c[2 * ng + 1], aq[kc][0], aq[kc][1], aq[kc][2], aq[kc][3], b[2], b[3]);
                }
            }

            if (jj0 + 63 > wq0 + PMEM) {
                int r0 = wq0 + grp, r1 = r0 + 8;
                #pragma unroll
                for (int nf = 0; nf < 8; nf++) {
                    int j0 = jj0 + nf * 8 + 2 * qid;
                    if (j0     - PMEM > r0) c[nf][0] = -1e30f;
                    if (j0 + 1 - PMEM > r0) c[nf][1] = -1e30f;
                    if (j0     - PMEM > r1) c[nf][2] = -1e30f;
                    if (j0 + 1 - PMEM > r1) c[nf][3] = -1e30f;
                }
            }

            float mt0 = -1e30f, mt1 = -1e30f;
            #pragma unroll
            for (int nf = 0; nf < 8; nf++) {
                mt0 = fmaxf(mt0, fmaxf(c[nf][0], c[nf][1]));
                mt1 = fmaxf(mt1, fmaxf(c[nf][2], c[nf][3]));
            }
            mt0 = fmaxf(mt0, __shfl_xor_sync(0xFFFFFFFFu, mt0, 1));
            mt0 = fmaxf(mt0, __shfl_xor_sync(0xFFFFFFFFu, mt0, 2));
            mt1 = fmaxf(mt1, __shfl_xor_sync(0xFFFFFFFFu, mt1, 1));
            mt1 = fmaxf(mt1, __shfl_xor_sync(0xFFFFFFFFu, mt1, 2));

            float nm0 = fmaxf(m0, mt0), nm1 = fmaxf(m1, mt1);
            float f0 = exp2p(m0 - nm0), f1 = exp2p(m1 - nm1);
            m0 = nm0; m1 = nm1;
            l0 *= f0; l1 *= f1;
            #pragma unroll
            for (int nf = 0; nf < 8; nf++) {
                o[nf][0] *= f0; o[nf][1] *= f0;
                o[nf][2] *= f1; o[nf][3] *= f1;
            }

            float s0 = 0.f, s1 = 0.f;
            #pragma unroll
            for (int nf = 0; nf < 8; nf++) {
                float p00 = exp2p(c[nf][0] - m0);
                float p01 = exp2p(c[nf][1] - m0);
                float p10 = exp2p(c[nf][2] - m1);
                float p11 = exp2p(c[nf][3] - m1);
                c[nf][0] = p00; c[nf][1] = p01; c[nf][2] = p10; c[nf][3] = p11;
                s0 += p00 + p01; s1 += p10 + p11;
            }
            s0 += __shfl_xor_sync(0xFFFFFFFFu, s0, 1);
            s0 += __shfl_xor_sync(0xFFFFFFFFu, s0, 2);
            s1 += __shfl_xor_sync(0xFFFFFFFFu, s1, 1);
            s1 += __shfl_xor_sync(0xFFFFFFFFu, s1, 2);
            l0 += s0; l1 += s1;

            unsigned ph[4][4];
            #pragma unroll
            for (int kc = 0; kc < 4; kc++) {
                ph[kc][0] = packh2(c[2 * kc    ][0], c[2 * kc    ][1]);
                ph[kc][1] = packh2(c[2 * kc    ][2], c[2 * kc    ][3]);
                ph[kc][2] = packh2(c[2 * kc + 1][0], c[2 * kc + 1][1]);
                ph[kc][3] = packh2(c[2 * kc + 1][2], c[2 * kc + 1][3]);
            }

            #pragma unroll
            for (int kc = 0; kc < 4; kc++) {
                #pragma unroll
                for (int dg = 0; dg < 4; dg++) {
                    unsigned b[4];
                    ldsm4t(b, sVb + (unsigned)((kc * 16 + fRow) * SH2 + dg * 16 + fCol) * 2);
                    mma_f16(o[2 * dg    ], ph[kc][0], ph[kc][1], ph[kc][2], ph[kc][3], b[0], b[1]);
                    mma_f16(o[2 * dg + 1], ph[kc][0], ph[kc][1], ph[kc][2], ph[kc][3], b[2], b[3]);
                }
            }
        }
    }

    float inv0 = 1.0f / l0, inv1 = 1.0f / l1;
    int bw = bwh >> 4, h = bwh & 15;
    int r0 = wq0 + grp, r1 = r0 + 8;
    __half* out0 = AO + (size_t)(bw * SEG + r0) * DIM + h * DH;
    __half* out1 = AO + (size_t)(bw * SEG + r1) * DIM + h * DH;
    #pragma unroll
    for (int nf = 0; nf < 8; nf++) {
        int col = nf * 8 + 2 * qid;
        *(unsigned*)(out0 + col) = packh2(o[nf][0] * inv0, o[nf][1] * inv0);
        *(unsigned*)(out1 + col) = packh2(o[nf][2] * inv1, o[nf][3] * inv1);
    }
}

// ---------------- launch ----------------
extern "C" void kernel_launch(void* const* d_in, const int* in_sizes, int n_in,
                              void* d_out, int out_size) {
    const float* seq   = (const float*)d_in[0];
    const float* g     = (const float*)d_in[1];
    const float* w_qkv = (const float*)d_in[2];
    const float* w_out = (const float*)d_in[3];
    const float* pm    = (const float*)d_in[4];
    float* out = (float*)d_out;

    __half *xnh, *whq, *who, *aoh, *q, *k, *v;
    float2* rope;
    cudaGetSymbolAddress((void**)&xnh, g_xnh);
    cudaGetSymbolAddress((void**)&whq, g_whq);
    cudaGetSymbolAddress((void**)&who, g_who);
    cudaGetSymbolAddress((void**)&q,   g_q);
    cudaGetSymbolAddress((void**)&k,   g_k);
    cudaGetSymbolAddress((void**)&v,   g_v);
    cudaGetSymbolAddress((void**)&aoh, g_aoh);
    cudaGetSymbolAddress((void**)&rope, g_rope);

    static int smem_set = 0;
    if (!smem_set) {
        cudaFuncSetAttribute(hgemm<true>,  cudaFuncAttributeMaxDynamicSharedMemorySize, GEMM_SMEM);
        cudaFuncSetAttribute(hgemm<false>, cudaFuncAttributeMaxDynamicSharedMemorySize, GEMM_SMEM);
        cudaFuncSetAttribute(attn_tc, cudaFuncAttributeMaxDynamicSharedMemorySize, ATT_SMEM);
        smem_set = 1;
    }

    // hgemm<true> placed 4th — profiler captures the 4th launch
    f2h_kernel<<<(3 * DIM * DIM / 4 + 255) / 256, 256>>>(w_qkv, whq, 3 * DIM * DIM / 4);
    rope_init<<<(NSEQ * 32 + 255) / 256, 256>>>(rope);
    rmsnorm_kernel<<<ROWS, 256>>>(seq, g, xnh);
    hgemm<true><<<dim3(3 * DIM / BN, ROWS / BM), 256, GEMM_SMEM>>>(xnh, whq, nullptr, q, k, v, rope, 3 * DIM, DIM);
    pm_fill<<<BW * HEADS, 1024>>>(pm, k, v);
    f2h_kernel<<<(DIM * DIM / 4 + 255) / 256, 256>>>(w_out, who, DIM * DIM / 4);
    attn_tc<<<dim3(4, BW * HEADS), 256, ATT_SMEM>>>(q, k, v, aoh);
    hgemm<false><<<dim3(DIM / BN, ROWS / BM), 256, GEMM_SMEM>>>(aoh, who, out, nullptr, nullptr, nullptr, nullptr, DIM, DIM);
}

// round 17
// speedup vs baseline: 1.1580x; 1.0181x over previous
#include <cuda_runtime.h>
#include <cuda_fp16.h>
#include <cstdint>
#include <math.h>

#define DIM    1024
#define HEADS  16
#define DH     64
#define SEG    512
#define PMEM   16
#define BATCH  2
#define NSEQ   4096
#define WSEG   (NSEQ / SEG)       // 8
#define BW     (BATCH * WSEG)     // 16
#define ROWS   (BATCH * NSEQ)     // 8192
#define KV     (SEG + PMEM)       // 528
#define RMS_EPS 1.1920929e-07f
#define QSC (0.125f * 1.4426950408889634f)

// ---------------- scratch (no cudaMalloc allowed) ----------------
__device__ __half g_xnh[(size_t)ROWS * DIM];
__device__ __half g_whq[(size_t)3 * DIM * DIM];
__device__ __half g_who[(size_t)DIM * DIM];
__device__ __half g_q  [(size_t)BW * HEADS * SEG * DH];
__device__ __half g_k  [(size_t)BW * HEADS * KV  * DH];
__device__ __half g_v  [(size_t)BW * HEADS * KV  * DH];
__device__ __half g_aoh[(size_t)ROWS * DIM];
__device__ float2 g_rope[(size_t)NSEQ * 32];     // [npos][d/2] = (cos, sin)

// ---------------- helpers ----------------
__device__ __forceinline__ float exp2p(float y) {
    y = fmaxf(y, -126.0f);
    float z = y + 12582912.0f;
    int   n = __float_as_int(z) - 0x4B400000;
    float f = y - (z - 12582912.0f);
    float p = 1.33336e-3f;
    p = fmaf(p, f, 9.61813e-3f);
    p = fmaf(p, f, 5.55041e-2f);
    p = fmaf(p, f, 2.40226502e-1f);
    p = fmaf(p, f, 6.93147182e-1f);
    p = fmaf(p, f, 1.0f);
    return p * __int_as_float((n + 127) << 23);
}

__device__ __forceinline__ void mma_f16(float c[4], unsigned a0, unsigned a1, unsigned a2,
                                        unsigned a3, unsigned b0, unsigned b1) {
    asm volatile(
        "mma.sync.aligned.m16n8k16.row.col.f32.f16.f16.f32 "
        "{%0,%1,%2,%3}, {%4,%5,%6,%7}, {%8,%9}, {%0,%1,%2,%3};"
        : "+f"(c[0]), "+f"(c[1]), "+f"(c[2]), "+f"(c[3])
        : "r"(a0), "r"(a1), "r"(a2), "r"(a3), "r"(b0), "r"(b1));
}

__device__ __forceinline__ void ldsm4(unsigned r[4], unsigned addr) {
    asm volatile("ldmatrix.sync.aligned.m8n8.x4.shared.b16 {%0,%1,%2,%3}, [%4];"
                 : "=r"(r[0]), "=r"(r[1]), "=r"(r[2]), "=r"(r[3]) : "r"(addr));
}

__device__ __forceinline__ void ldsm4t(unsigned r[4], unsigned addr) {
    asm volatile("ldmatrix.sync.aligned.m8n8.x4.trans.shared.b16 {%0,%1,%2,%3}, [%4];"
                 : "=r"(r[0]), "=r"(r[1]), "=r"(r[2]), "=r"(r[3]) : "r"(addr));
}

__device__ __forceinline__ unsigned packh2(float lo, float hi) {
    __half2 h = __floats2half2_rn(lo, hi);
    return *(unsigned*)&h;
}

__device__ __forceinline__ void cpasync16(unsigned dst, const void* src) {
    asm volatile("cp.async.ca.shared.global [%0], [%1], 16;" :: "r"(dst), "l"(src));
}
__device__ __forceinline__ void cpasync16z(unsigned dst, const void* src, bool valid) {
    unsigned v = valid ? 16u : 0u;
    asm volatile("cp.async.ca.shared.global [%0], [%1], 16, %2;"
                 :: "r"(dst), "l"(src), "r"(v));
}
__device__ __forceinline__ void cpcommit() {
    asm volatile("cp.async.commit_group;");
}
template <int N>
__device__ __forceinline__ void cpwait() {
    asm volatile("cp.async.wait_group %0;" :: "n"(N));
}

// ---------------- RoPE table init ----------------
__global__ __launch_bounds__(256) void rope_init(float2* __restrict__ tab) {
    int i = blockIdx.x * 256 + threadIdx.x;     // 0..131071
    if (i < NSEQ * 32) {
        int npos = i >> 5;
        int f = i & 31;
        float inv = 1.0f / powf(10000.0f, (float)(2 * f) * (1.0f / 64.0f));
        float sn, cs;
        sincosf((float)npos * inv, &sn, &cs);
        tab[i] = make_float2(cs, sn);
    }
}

// ---------------- weight fp32 -> fp16 ----------------
__global__ __launch_bounds__(256) void f2h_kernel(const float* __restrict__ s,
                                                  __half* __restrict__ d, int n4) {
    int i = blockIdx.x * 256 + threadIdx.x;
    if (i < n4) {
        float4 v = ((const float4*)s)[i];
        __half2 h0 = __floats2half2_rn(v.x, v.y);
        __half2 h1 = __floats2half2_rn(v.z, v.w);
        ((uint2*)d)[i] = make_uint2(*(unsigned*)&h0, *(unsigned*)&h1);
    }
}

// ---------------- RMSNorm (fp16 out) ----------------
__global__ __launch_bounds__(256) void rmsnorm_kernel(const float* __restrict__ seq,
                                                      const float* __restrict__ g,
                                                      __half* __restrict__ xnh) {
    int row = blockIdx.x;
    int tid = threadIdx.x;
    const float4* in = (const float4*)(seq + (size_t)row * DIM);
    float4 v = in[tid];
    float ss = v.x * v.x + v.y * v.y + v.z * v.z + v.w * v.w;
    #pragma unroll
    for (int o = 16; o; o >>= 1) ss += __shfl_xor_sync(0xFFFFFFFFu, ss, o);
    __shared__ float wsum[8];
    __shared__ float srms;
    if ((tid & 31) == 0) wsum[tid >> 5] = ss;
    __syncthreads();
    if (tid == 0) {
        float t = 0.f;
        #pragma unroll
        for (int i = 0; i < 8; i++) t += wsum[i];
        srms = rsqrtf(t * (1.0f / DIM) + RMS_EPS);
    }
    __syncthreads();
    float r = srms;
    float4 gv = ((const float4*)g)[tid];
    __half2 h0 = __floats2half2_rn(v.x * r * gv.x, v.y * r * gv.y);
    __half2 h1 = __floats2half2_rn(v.z * r * gv.z, v.w * r * gv.w);
    ((uint2*)(xnh + (size_t)row * DIM))[tid] = make_uint2(*(unsigned*)&h0, *(unsigned*)&h1);
}

// ---------------- FP16 GEMM: C = A * B^T, 128x128 CTA, 2-stage single-sync --------
// QKV=true: fused RoPE (smem-staged table) + segment scatter epilogue into q/k/v.
#define BM 128
#define BN 128
#define KC 64
#define HS 72
#define SSZ (BM * HS)
#define GEMM_SMEM (2 * 2 * SSZ * 2)     // 73728
#define RSTR 33                          // rope smem stride (float2)

template <bool QKV>
__global__ __launch_bounds__(256) void hgemm(const __half* __restrict__ A,
                                             const __half* __restrict__ Bm,
                                             float* __restrict__ C,
                                             __half* __restrict__ qo,
                                             __half* __restrict__ ko,
                                             __half* __restrict__ vo,
                                             const float2* __restrict__ rope,
                                             int Nn, int K) {
    extern __shared__ __half sh[];
    unsigned smem_base = (unsigned)__cvta_generic_to_shared(sh);

    int tid = threadIdx.x;
    int bm = blockIdx.y * BM;
    int bn = blockIdx.x * BN;

    int wid  = tid >> 5;
    int lane = tid & 31;
    int warp_m = (wid & 3) * 32;
    int warp_n = (wid >> 2) * 64;
    int grp = lane >> 2;
    int qid = lane & 3;

    float c[2][8][4];
    #pragma unroll
    for (int i = 0; i < 2; i++)
        #pragma unroll
        for (int j = 0; j < 8; j++)
            #pragma unroll
            for (int u = 0; u < 4; u++) c[i][j][u] = 0.f;

    const int NT = K / KC;

    auto issue = [&](int kt, int s) {
        unsigned sb = smem_base + (unsigned)(s * 2 * SSZ * 2);
        int k0 = kt * KC;
        #pragma unroll
        for (int i = 0; i < 4; i++) {
            int chunk = tid + 256 * i;
            int row = chunk >> 3;
            int c8 = (chunk & 7) * 8;
            unsigned off = (unsigned)(row * HS + c8) * 2;
            cpasync16(sb + off, A + (size_t)(bm + row) * K + k0 + c8);
            cpasync16(sb + (unsigned)(SSZ * 2) + off, Bm + (size_t)(bn + row) * K + k0 + c8);
        }
        cpcommit();
    };

    int aRow = warp_m + (lane & 15);
    int aCol = (lane & 16) >> 1;
    int nOff = (lane & 7) | ((lane & 16) >> 1);
    int kOff = lane & 8;

    issue(0, 0);

    for (int kt = 0; kt < NT; kt++) {
        cpwait<0>();
        __syncthreads();
        if (kt + 1 < NT) issue(kt + 1, (kt + 1) & 1);

        unsigned sb = smem_base + (unsigned)((kt & 1) * 2 * SSZ * 2);
        unsigned aAddr = sb + (unsigned)(aRow * HS + aCol) * 2;
        unsigned bAddr = sb + (unsigned)(SSZ * 2) + (unsigned)((warp_n + nOff) * HS + kOff) * 2;

        #pragma unroll
        for (int ks = 0; ks < 4; ks++) {
            unsigned a0[4], a1[4];
            ldsm4(a0, aAddr + ks * 32);
            ldsm4(a1, aAddr + (unsigned)(16 * HS * 2) + ks * 32);
            unsigned bf[4][4];
            #pragma unroll
            for (int nt = 0; nt < 4; nt++)
                ldsm4(bf[nt], bAddr + (unsigned)(nt * 16 * HS * 2) + ks * 32);
            #pragma unroll
            for (int nt = 0; nt < 4; nt++) {
                mma_f16(c[0][2 * nt    ], a0[0], a0[1], a0[2], a0[3], bf[nt][0], bf[nt][1]);
                mma_f16(c[0][2 * nt + 1], a0[0], a0[1], a0[2], a0[3], bf[nt][2], bf[nt][3]);
                mma_f16(c[1][2 * nt    ], a1[0], a1[1], a1[2], a1[3], bf[nt][0], bf[nt][1]);
                mma_f16(c[1][2 * nt + 1], a1[0], a1[1], a1[2], a1[3], bf[nt][2], bf[nt][3]);
            }
        }
    }

    if (!QKV) {
        #pragma unroll
        for (int mf = 0; mf < 2; mf++) {
            int row0 = bm + warp_m + mf * 16 + grp;
            #pragma unroll
            for (int nf = 0; nf < 8; nf++) {
                int col = bn + warp_n + nf * 8 + qid * 2;
                *(float2*)(C + (size_t)row0 * Nn + col)       = make_float2(c[mf][nf][0], c[mf][nf][1]);
                *(float2*)(C + (size_t)(row0 + 8) * Nn + col) = make_float2(c[mf][nf][2], c[mf][nf][3]);
            }
        }
    } else {
        // stage this CTA's rope slice into (now-dead) stage smem, padded stride
        float2* srope = (float2*)sh;
        if (bn < 2048) {
            __syncthreads();                       // all warps done with stage smem
            int npos0 = bm & 4095;                 // CTA spans one batch (bm % 128 == 0)
            for (int i = tid; i < 128 * 32; i += 256) {
                int row = i >> 5, f = i & 31;
                srope[row * RSTR + f] = rope[(size_t)(npos0 + row) * 32 + f];
            }
            __syncthreads();
        }

        int which = (bn + warp_n) >> 10;           // uniform per warp
        #pragma unroll
        for (int mf = 0; mf < 2; mf++) {
            #pragma unroll
            for (int sub = 0; sub < 2; sub++) {
                int lr = warp_m + mf * 16 + grp + sub * 8;   // 0..127 local row
                int m = bm + lr;
                int b = m >> 12;
                int npos = m & 4095;
                int w = npos >> 9;
                int sidx = npos & 511;
                int bwx = (b * WSEG + w) * HEADS;
                #pragma unroll
                for (int nf = 0; nf < 8; nf++) {
                    int col = bn + warp_n + nf * 8 + qid * 2;
                    int h = (col >> 6) & 15;
                    int d = col & 63;
                    float x = c[mf][nf][2 * sub], y = c[mf][nf][2 * sub + 1];
                    int bwh = bwx + h;
                    if (which == 2) {
                        *(unsigned*)(vo + ((size_t)bwh * KV + PMEM + sidx) * DH + d) = packh2(x, y);
                    } else {
                        float2 rt = srope[lr * RSTR + (d >> 1)];
                        float rx = x * rt.x - y * rt.y;
                        float ry = y * rt.x + x * rt.y;
                        if (which == 0)
                            *(unsigned*)(qo + ((size_t)bwh * SEG + sidx) * DH + d) = packh2(rx * QSC, ry * QSC);
                        else
                            *(unsigned*)(ko + ((size_t)bwh * KV + PMEM + sidx) * DH + d) = packh2(rx, ry);
                    }
                }
            }
        }
    }
}

// ---------------- persistent-memory prepend (half) ----------------
__global__ __launch_bounds__(1024) void pm_fill(const float* __restrict__ pm,
                                                __half* __restrict__ k,
                                                __half* __restrict__ v) {
    int bwh = blockIdx.x;
    int h = bwh & 15;
    int t = threadIdx.x;
    int p = t >> 6;
    int d = t & 63;
    float kv_ = pm[((size_t)h * PMEM + p) * DH + d];
    float vv_ = pm[(size_t)HEADS * PMEM * DH + ((size_t)h * PMEM + p) * DH + d];
    k[((size_t)bwh * KV + p) * DH + d] = __float2half(kv_);
    v[((size_t)bwh * KV + p) * DH + d] = __float2half(vv_);
}

// ---------------- fp16 flash attention, 2-stage single-sync cp.async --------------
#define SH2 72
#define QBYTES (128 * SH2 * 2)
#define KVBYTES (64 * SH2 * 2)
#define ATT_SMEM (QBYTES + 4 * KVBYTES)

__global__ __launch_bounds__(256) void attn_tc(const __half* __restrict__ Q,
                                               const __half* __restrict__ K,
                                               const __half* __restrict__ V,
                                               __half* __restrict__ AO) {
    extern __shared__ __half ash[];
    unsigned sbase = (unsigned)__cvta_generic_to_shared(ash);

    const int tid  = threadIdx.x;
    const int wid  = tid >> 5;
    const int lane = tid & 31;
    const int grp  = lane >> 2;
    const int qid  = lane & 3;
    const int bwh  = blockIdx.y;
    const int q0   = blockIdx.x * 128;
    const int wq0  = q0 + wid * 16;

    const __half* Qb = Q + (size_t)bwh * SEG * DH;
    const __half* Kb = K + (size_t)bwh * KV * DH;
    const __half* Vb = V + (size_t)bwh * KV * DH;

    const int r  = tid >> 2;
    const int c4 = tid & 3;

    int jmax = q0 + 128 + PMEM;
    if (jmax > KV) jmax = KV;
    int ntiles = (jmax + 63) >> 6;

    auto issueKV = [&](int t, int s) {
        unsigned kb = sbase + (unsigned)(QBYTES + s * 2 * KVBYTES);
        unsigned vb = kb + KVBYTES;
        int jj = t * 64 + r;
        bool valid = jj < KV;
        int jjc = valid ? jj : (KV - 1);
        const __half* kg = Kb + (size_t)jjc * DH + c4 * 16;
        const __half* vg = Vb + (size_t)jjc * DH + c4 * 16;
        unsigned off = (unsigned)(r * SH2 + c4 * 16) * 2;
        cpasync16z(kb + off,      kg,     valid);
        cpasync16z(kb + off + 16, kg + 8, valid);
        cpasync16z(vb + off,      vg,     valid);
        cpasync16z(vb + off + 16, vg + 8, valid);
        cpcommit();
    };

    issueKV(0, 0);

    {
        __half* sQp = ash;
        #pragma unroll
        for (int i = 0; i < 4; i++) {
            int chunk = tid + 256 * i;
            int row = chunk >> 3;
            int off = (chunk & 7) * 8;
            *(uint4*)(sQp + row * SH2 + off) = *(const uint4*)(Qb + (size_t)(q0 + row) * DH + off);
        }
    }
    __syncthreads();

    unsigned aq[4][4];
    {
        int aRow = wid * 16 + (lane & 15);
        int aCol = (lane & 16) >> 1;
        #pragma unroll
        for (int kc = 0; kc < 4; kc++)
            ldsm4(aq[kc], sbase + (unsigned)(aRow * SH2 + kc * 16 + aCol) * 2);
    }

    float o[8][4];
    #pragma unroll
    for (int nf = 0; nf < 8; nf++)
        #pragma unroll
        for (int u = 0; u < 4; u++) o[nf][u] = 0.f;
    float m0 = -1e30f, m1 = -1e30f, l0 = 0.f, l1 = 0.f;

    const int fRow = lane & 15;
    const int fCol = (lane & 16) >> 1;
    const int nRow = (lane & 7) | ((lane & 16) >> 1);
    const int kOff = lane & 8;

    for (int t = 0; t < ntiles; t++) {
        int jj0 = t << 6;
        cpwait<0>();
        __syncthreads();
        if (t + 1 < ntiles) issueKV(t + 1, (t + 1) & 1);

        unsigned sKb = sbase + (unsigned)(QBYTES + (t & 1) * 2 * KVBYTES);
        unsigned sVb = sKb + KVBYTES;

        if (jj0 <= wq0 + 15 + PMEM) {
            float c[8][4];
            #pragma unroll
            for (int nf = 0; nf < 8; nf++)
                #pragma unroll
                for (int u = 0; u < 4; u++) c[nf][u] = 0.f;

            #pragma unroll
            for (int kc = 0; kc < 4; kc++) {
                #pragma unroll
                for (int ng = 0; ng < 4; ng++) {
                    unsigned b[4];
                    ldsm4(b, sKb + (unsigned)((ng * 16 + nRow) * SH2 + kc * 16 + kOff) * 2);
                    mma_f16(c[2 * ng    ], aq[kc][0], aq[kc][1], aq[kc][2], aq[kc][3], b[0], b[1]);
                    mma_f16(c[2 * ng + 1], aq[kc][0], aq[kc][1], aq[kc][2], aq[kc][3], b[2], b[3]);
                }
            }

            if (jj0 + 63 > wq0 + PMEM) {
                int r0 = wq0 + grp, r1 = r0 + 8;
                #pragma unroll
                for (int nf = 0; nf < 8; nf++) {
                    int j0 = jj0 + nf * 8 + 2 * qid;
                    if (j0     - PMEM > r0) c[nf][0] = -1e30f;
                    if (j0 + 1 - PMEM > r0) c[nf][1] = -1e30f;
                    if (j0     - PMEM > r1) c[nf][2] = -1e30f;
                    if (j0 + 1 - PMEM > r1) c[nf][3] = -1e30f;
                }
            }

            float mt0 = -1e30f, mt1 = -1e30f;
            #pragma unroll
            for (int nf = 0; nf < 8; nf++) {
                mt0 = fmaxf(mt0, fmaxf(c[nf][0], c[nf][1]));
                mt1 = fmaxf(mt1, fmaxf(c[nf][2], c[nf][3]));
            }
            mt0 = fmaxf(mt0, __shfl_xor_sync(0xFFFFFFFFu, mt0, 1));
            mt0 = fmaxf(mt0, __shfl_xor_sync(0xFFFFFFFFu, mt0, 2));
            mt1 = fmaxf(mt1, __shfl_xor_sync(0xFFFFFFFFu, mt1, 1));
            mt1 = fmaxf(mt1, __shfl_xor_sync(0xFFFFFFFFu, mt1, 2));

            float nm0 = fmaxf(m0, mt0), nm1 = fmaxf(m1, mt1);
            float f0 = exp2p(m0 - nm0), f1 = exp2p(m1 - nm1);
            m0 = nm0; m1 = nm1;
            l0 *= f0; l1 *= f1;
            #pragma unroll
            for (int nf = 0; nf < 8; nf++) {
                o[nf][0] *= f0; o[nf][1] *= f0;
                o[nf][2] *= f1; o[nf][3] *= f1;
            }

            float s0 = 0.f, s1 = 0.f;
            #pragma unroll
            for (int nf = 0; nf < 8; nf++) {
                float p00 = exp2p(c[nf][0] - m0);
                float p01 = exp2p(c[nf][1] - m0);
                float p10 = exp2p(c[nf][2] - m1);
                float p11 = exp2p(c[nf][3] - m1);
                c[nf][0] = p00; c[nf][1] = p01; c[nf][2] = p10; c[nf][3] = p11;
                s0 += p00 + p01; s1 += p10 + p11;
            }
            s0 += __shfl_xor_sync(0xFFFFFFFFu, s0, 1);
            s0 += __shfl_xor_sync(0xFFFFFFFFu, s0, 2);
            s1 += __shfl_xor_sync(0xFFFFFFFFu, s1, 1);
            s1 += __shfl_xor_sync(0xFFFFFFFFu, s1, 2);
            l0 += s0; l1 += s1;

            unsigned ph[4][4];
            #pragma unroll
            for (int kc = 0; kc < 4; kc++) {
                ph[kc][0] = packh2(c[2 * kc    ][0], c[2 * kc    ][1]);
                ph[kc][1] = packh2(c[2 * kc    ][2], c[2 * kc    ][3]);
                ph[kc][2] = packh2(c[2 * kc + 1][0], c[2 * kc + 1][1]);
                ph[kc][3] = packh2(c[2 * kc + 1][2], c[2 * kc + 1][3]);
            }

            #pragma unroll
            for (int kc = 0; kc < 4; kc++) {
                #pragma unroll
                for (int dg = 0; dg < 4; dg++) {
                    unsigned b[4];
                    ldsm4t(b, sVb + (unsigned)((kc * 16 + fRow) * SH2 + dg * 16 + fCol) * 2);
                    mma_f16(o[2 * dg    ], ph[kc][0], ph[kc][1], ph[kc][2], ph[kc][3], b[0], b[1]);
                    mma_f16(o[2 * dg + 1], ph[kc][0], ph[kc][1], ph[kc][2], ph[kc][3], b[2], b[3]);
                }
            }
        }
    }

    float inv0 = 1.0f / l0, inv1 = 1.0f / l1;
    int bw = bwh >> 4, h = bwh & 15;
    int r0 = wq0 + grp, r1 = r0 + 8;
    __half* out0 = AO + (size_t)(bw * SEG + r0) * DIM + h * DH;
    __half* out1 = AO + (size_t)(bw * SEG + r1) * DIM + h * DH;
    #pragma unroll
    for (int nf = 0; nf < 8; nf++) {
        int col = nf * 8 + 2 * qid;
        *(unsigned*)(out0 + col) = packh2(o[nf][0] * inv0, o[nf][1] * inv0);
        *(unsigned*)(out1 + col) = packh2(o[nf][2] * inv1, o[nf][3] * inv1);
    }
}

// ---------------- launch ----------------
extern "C" void kernel_launch(void* const* d_in, const int* in_sizes, int n_in,
                              void* d_out, int out_size) {
    const float* seq   = (const float*)d_in[0];
    const float* g     = (const float*)d_in[1];
    const float* w_qkv = (const float*)d_in[2];
    const float* w_out = (const float*)d_in[3];
    const float* pm    = (const float*)d_in[4];
    float* out = (float*)d_out;

    __half *xnh, *whq, *who, *aoh, *q, *k, *v;
    float2* rope;
    cudaGetSymbolAddress((void**)&xnh, g_xnh);
    cudaGetSymbolAddress((void**)&whq, g_whq);
    cudaGetSymbolAddress((void**)&who, g_who);
    cudaGetSymbolAddress((void**)&q,   g_q);
    cudaGetSymbolAddress((void**)&k,   g_k);
    cudaGetSymbolAddress((void**)&v,   g_v);
    cudaGetSymbolAddress((void**)&aoh, g_aoh);
    cudaGetSymbolAddress((void**)&rope, g_rope);

    static int smem_set = 0;
    if (!smem_set) {
        cudaFuncSetAttribute(hgemm<true>,  cudaFuncAttributeMaxDynamicSharedMemorySize, GEMM_SMEM);
        cudaFuncSetAttribute(hgemm<false>, cudaFuncAttributeMaxDynamicSharedMemorySize, GEMM_SMEM);
        cudaFuncSetAttribute(attn_tc, cudaFuncAttributeMaxDynamicSharedMemorySize, ATT_SMEM);
        smem_set = 1;
    }

    // hgemm<true> placed 4th — profiler captures the 4th launch
    f2h_kernel<<<(3 * DIM * DIM / 4 + 255) / 256, 256>>>(w_qkv, whq, 3 * DIM * DIM / 4);
    rope_init<<<(NSEQ * 32 + 255) / 256, 256>>>(rope);
    rmsnorm_kernel<<<ROWS, 256>>>(seq, g, xnh);
    hgemm<true><<<dim3(3 * DIM / BN, ROWS / BM), 256, GEMM_SMEM>>>(xnh, whq, nullptr, q, k, v, rope, 3 * DIM, DIM);
    pm_fill<<<BW * HEADS, 1024>>>(pm, k, v);
    f2h_kernel<<<(DIM * DIM / 4 + 255) / 256, 256>>>(w_out, who, DIM * DIM / 4);
    attn_tc<<<dim3(4, BW * HEADS), 256, ATT_SMEM>>>(q, k, v, aoh);
    hgemm<false><<<dim3(DIM / BN, ROWS / BM), 256, GEMM_SMEM>>>(aoh, who, out, nullptr, nullptr, nullptr, nullptr, DIM, DIM);
}